// round 11
// baseline (speedup 1.0000x reference)
#include <cuda_runtime.h>
#include <math.h>

#define BB 64
#define CC 768
#define HH 64
#define WW 64
#define PLANE (HH*WW)           // 4096

// Hermitian-symmetrized full-plane gate, ortho^2 scale folded.
// Layout permuted for LDG.128 in the column pass:
//   plane element (kh, kw) stored at  [c][ kw*64 + (kh&7)*8 + (kh>>3) ]
// so thread j's 8 gate values (kh = j+8*k2, k2=0..7) are contiguous.
__device__ float2 g_geff[CC * 64 * 64];

// ---------------------------------------------------------------------------
// complex helpers (scalar float2 engine)
// ---------------------------------------------------------------------------
__device__ __forceinline__ float2 cadd(float2 a, float2 b){ return make_float2(a.x+b.x, a.y+b.y); }
__device__ __forceinline__ float2 csub(float2 a, float2 b){ return make_float2(a.x-b.x, a.y-b.y); }
__device__ __forceinline__ float2 cmul(float2 a, float2 b){
    return make_float2(fmaf(a.x,b.x,-a.y*b.y), fmaf(a.x,b.y, a.y*b.x));
}
template<int DIR>
__device__ __forceinline__ float2 muli(float2 a){
    return (DIR < 0) ? make_float2(a.y, -a.x) : make_float2(-a.y, a.x);
}

// ---------------------------------------------------------------------------
// 8-point complex FFT on registers, natural order in/out. Unnormalized.
// ---------------------------------------------------------------------------
template<int DIR>
__device__ __forceinline__ void fft8(float2 v[8]){
    const float s = 0.70710678118654752440f;
    float2 b0 = cadd(v[0], v[4]);
    float2 b1 = cadd(v[1], v[5]);
    float2 b2 = cadd(v[2], v[6]);
    float2 b3 = cadd(v[3], v[7]);
    float2 b4 = csub(v[0], v[4]);
    float2 b5 = csub(v[1], v[5]);
    float2 b6 = csub(v[2], v[6]);
    float2 b7 = csub(v[3], v[7]);
    b5 = cmul(b5, make_float2( s, DIR * s));
    b6 = muli<DIR>(b6);
    b7 = cmul(b7, make_float2(-s, DIR * s));
    float2 c0 = cadd(b0, b2), c2 = csub(b0, b2);
    float2 c1 = cadd(b1, b3), c3 = csub(b1, b3);
    c3 = muli<DIR>(c3);
    float2 c4 = cadd(b4, b6), c6 = csub(b4, b6);
    float2 c5 = cadd(b5, b7), c7 = csub(b5, b7);
    c7 = muli<DIR>(c7);
    float2 d0 = cadd(c0, c1), d1 = csub(c0, c1);
    float2 d2 = cadd(c2, c3), d3 = csub(c2, c3);
    float2 d4 = cadd(c4, c5), d5 = csub(c4, c5);
    float2 d6 = cadd(c6, c7), d7 = csub(c6, c7);
    v[0]=d0; v[1]=d4; v[2]=d2; v[3]=d6; v[4]=d1; v[5]=d5; v[6]=d3; v[7]=d7;
}

// ---------------------------------------------------------------------------
// 8x8 transpose across the 8 lanes of a group (wavefront-optimal: 24 SHFL)
// ---------------------------------------------------------------------------
__device__ __forceinline__ void transpose8(float2 v[8], unsigned mask, int lane8){
    #pragma unroll
    for (int m = 4; m >= 1; m >>= 1){
        bool up = (lane8 & m) != 0;
        #pragma unroll
        for (int i = 0; i < 8; i++){
            if ((i & m) == 0){
                int lo = i, hi = i | m;
                float2 t = up ? v[lo] : v[hi];
                t.x = __shfl_xor_sync(mask, t.x, m);
                t.y = __shfl_xor_sync(mask, t.y, m);
                if (up) v[lo] = t; else v[hi] = t;
            }
        }
    }
}

// ---------------------------------------------------------------------------
// 64-pt FFT over 8 lanes (radix 8x8 four-step).
// Layout invariant (in AND out): element index = 8*reg + lane. Chains freely.
// twf[m-1] = e^{-2*pi*i * j*m / 64}, m = 1..7 (m=0 is unity, not stored)
// ---------------------------------------------------------------------------
template<int DIR>
__device__ __forceinline__ void fft64(float2 v[8], const float2 twf[7],
                                      unsigned mask, int j){
    fft8<DIR>(v);
    #pragma unroll
    for (int m = 1; m < 8; m++){
        float2 w = twf[m-1];
        if (DIR > 0) w.y = -w.y;
        v[m] = cmul(v[m], w);
    }
    transpose8(v, mask, j);
    fft8<DIR>(v);
}

// ---------------------------------------------------------------------------
// prep: Hermitian-symmetrized full-plane gate, 1/4096 folded, permuted layout
// ---------------------------------------------------------------------------
__global__ void prep_geff_kernel(const float* __restrict__ w){
    int idx = blockIdx.x * blockDim.x + threadIdx.x;
    if (idx >= CC * 64 * 64) return;
    int c   = idx >> 12;
    int rem = idx & 4095;
    int kw  = rem >> 6;
    int kh  = rem & 63;
    const float2* W = (const float2*)w;   // float2 index = (kh*33 + k)*CC + c
    float2 g;
    if (kw <= 32){
        g = W[(kh * 33 + kw) * CC + c];
        if (kw == 0 || kw == 32){
            float2 m = W[(((64 - kh) & 63) * 33 + kw) * CC + c];
            g.x = 0.5f * (g.x + m.x);
            g.y = 0.5f * (g.y - m.y);
        }
    } else {
        float2 m = W[(((64 - kh) & 63) * 33 + (64 - kw)) * CC + c];
        g.x =  m.x;
        g.y = -m.y;
    }
    const float S = 1.0f / 4096.0f;
    g.x *= S; g.y *= S;
    // permuted store: thread j in main kernel reads (kh = j + 8*k2) contiguously
    int pos = (c << 12) + (kw << 6) + ((kh & 7) << 3) + (kh >> 3);
    g_geff[pos] = g;
}

// ---------------------------------------------------------------------------
// main: one CTA per plane-PAIR (batches 2bp, 2bp+1 at channel c). z = x0 + i*x1.
// Full complex 2D FFT -> Hermitian gate -> inverse; Re -> plane0, Im -> plane1.
// 256 threads = 32 groups of 8 lanes; each group: 2 rows, 2 cols, 2 rows.
// ---------------------------------------------------------------------------
__global__ __launch_bounds__(256, 4)
void sgn4_kernel(const float* __restrict__ x, float* __restrict__ out){
    __shared__ __align__(16) float2 Sg[64 * 66];   // [kw][h], row stride 66

    const int t    = threadIdx.x;
    const int j    = t & 7;
    const int g    = t >> 3;
    const int lane = t & 31;
    const unsigned mask = 0xFFu << (lane & 24);

    const int pc = blockIdx.x;            // bp*CC + c
    const int c  = pc % CC;
    const int bp = pc / CC;
    const float* xp0 = x + ((size_t)(2 * bp) * CC + c) * PLANE;
    const float* xp1 = xp0 + (size_t)CC * PLANE;
    float* op0 = out + ((size_t)(2 * bp) * CC + c) * PLANE;
    float* op1 = op0 + (size_t)CC * PLANE;

    // per-lane forward twiddles e^{-2pi i j*m/64}, m=1..7
    float2 twf[7];
    #pragma unroll
    for (int m = 1; m < 8; m++){
        float sv, cv;
        sincospif((float)(j * m) * (1.0f / 32.0f), &sv, &cv);
        twf[m-1] = make_float2(cv, -sv);
    }

    // ---------------- forward rows (W axis): rows g and g+32 ----------------
    #pragma unroll 1
    for (int it = 0; it < 2; it++){
        const int r = g + 32 * it;
        float2 v[8];
        #pragma unroll
        for (int n1 = 0; n1 < 8; n1++){
            int wdx = r * 64 + 8 * n1 + j;
            v[n1] = make_float2(xp0[wdx], xp1[wdx]);
        }
        fft64<-1>(v, twf, mask, j);               // v[k2] = Z[r][kw=j+8k2]
        #pragma unroll
        for (int k2 = 0; k2 < 8; k2++) Sg[(j + 8 * k2) * 66 + r] = v[k2];
    }
    __syncthreads();

    // ---- columns (H axis): fwd FFT -> gate -> inv FFT, chained in regs -----
    const float4* __restrict__ gbase = (const float4*)(g_geff + (size_t)c * 4096);
    #pragma unroll 1
    for (int it = 0; it < 2; it++){
        const int q = g + 32 * it;        // kw column
        float2 u[8];
        #pragma unroll
        for (int n1 = 0; n1 < 8; n1++) u[n1] = Sg[q * 66 + 8 * n1 + j];
        fft64<-1>(u, twf, mask, j);               // u[k2] = Xf[kh=j+8k2][q]
        // gate: 4x LDG.128 (permuted layout: (q*64 + j*8 + k2) float2s)
        const float4* gq = gbase + (q * 64 + j * 8) / 2;
        #pragma unroll
        for (int p = 0; p < 4; p++){
            float4 gg = gq[p];
            u[2*p]   = cmul(u[2*p],   make_float2(gg.x, gg.y));
            u[2*p+1] = cmul(u[2*p+1], make_float2(gg.z, gg.w));
        }
        fft64<1>(u, twf, mask, j);                // u[n2] = y[h=j+8n2][q]
        #pragma unroll
        for (int n2 = 0; n2 < 8; n2++) Sg[q * 66 + j + 8 * n2] = u[n2];
    }
    __syncthreads();

    // ---------------- inverse rows (W axis): Re->p0, Im->p1 -----------------
    #pragma unroll 1
    for (int it = 0; it < 2; it++){
        const int r = g + 32 * it;
        float2 v[8];
        #pragma unroll
        for (int n1 = 0; n1 < 8; n1++) v[n1] = Sg[(8 * n1 + j) * 66 + r];
        fft64<1>(v, twf, mask, j);                // v[k2] = z_out[r][w=j+8k2]
        #pragma unroll
        for (int k2 = 0; k2 < 8; k2++){
            int wdx = r * 64 + j + 8 * k2;
            op0[wdx] = v[k2].x;
            op1[wdx] = v[k2].y;
        }
    }
}

// ---------------------------------------------------------------------------
extern "C" void kernel_launch(void* const* d_in, const int* in_sizes, int n_in,
                              void* d_out, int out_size){
    const float* x;
    const float* w;
    if (in_sizes[0] == BB * CC * HH * WW){
        x = (const float*)d_in[0];
        w = (const float*)d_in[1];
    } else {
        x = (const float*)d_in[1];
        w = (const float*)d_in[0];
    }
    prep_geff_kernel<<<(CC * 64 * 64 + 255) / 256, 256>>>(w);
    sgn4_kernel<<<(BB / 2) * CC, 256>>>(x, (float*)d_out);
}

// round 12
// speedup vs baseline: 1.0456x; 1.0456x over previous
#include <cuda_runtime.h>
#include <math.h>

#define BB 64
#define CC 768
#define HH 64
#define WW 64
#define PLANE (HH*WW)           // 4096

// Hermitian-symmetrized full-plane gate, ortho^2 scale folded.
// Layout permuted for LDG.128 in the column pass:
//   plane element (kh, kw) stored at  [c][ kw*64 + (kh&7)*8 + (kh>>3) ]
__device__ float2 g_geff[CC * 64 * 64];

// ---------------------------------------------------------------------------
// complex helpers (scalar float2 engine)
// ---------------------------------------------------------------------------
__device__ __forceinline__ float2 cadd(float2 a, float2 b){ return make_float2(a.x+b.x, a.y+b.y); }
__device__ __forceinline__ float2 csub(float2 a, float2 b){ return make_float2(a.x-b.x, a.y-b.y); }
__device__ __forceinline__ float2 cmul(float2 a, float2 b){
    return make_float2(fmaf(a.x,b.x,-a.y*b.y), fmaf(a.x,b.y, a.y*b.x));
}
template<int DIR>
__device__ __forceinline__ float2 muli(float2 a){
    return (DIR < 0) ? make_float2(a.y, -a.x) : make_float2(-a.y, a.x);
}

// ---------------------------------------------------------------------------
// conflict-free corner-turn swizzle: logical (kw, h) -> physical float2 index.
// bank-pair = low4(h ^ s(kw)); s places kw bit0 in bank bit3 and kw bits1-2
// in bank bits1-2, so every access pattern used below is a (j, g-parity)
// bijection onto the 16 bank-pairs of a half-warp. No padding needed.
// ---------------------------------------------------------------------------
__device__ __forceinline__ int swz(int kw, int h){
    int s = ((kw & 1) << 3) | (kw & 6);
    return (kw << 6) + (h ^ s);
}

// ---------------------------------------------------------------------------
// 8-point complex FFT on registers, natural order in/out. Unnormalized.
// ---------------------------------------------------------------------------
template<int DIR>
__device__ __forceinline__ void fft8(float2 v[8]){
    const float s = 0.70710678118654752440f;
    float2 b0 = cadd(v[0], v[4]);
    float2 b1 = cadd(v[1], v[5]);
    float2 b2 = cadd(v[2], v[6]);
    float2 b3 = cadd(v[3], v[7]);
    float2 b4 = csub(v[0], v[4]);
    float2 b5 = csub(v[1], v[5]);
    float2 b6 = csub(v[2], v[6]);
    float2 b7 = csub(v[3], v[7]);
    b5 = cmul(b5, make_float2( s, DIR * s));
    b6 = muli<DIR>(b6);
    b7 = cmul(b7, make_float2(-s, DIR * s));
    float2 c0 = cadd(b0, b2), c2 = csub(b0, b2);
    float2 c1 = cadd(b1, b3), c3 = csub(b1, b3);
    c3 = muli<DIR>(c3);
    float2 c4 = cadd(b4, b6), c6 = csub(b4, b6);
    float2 c5 = cadd(b5, b7), c7 = csub(b5, b7);
    c7 = muli<DIR>(c7);
    float2 d0 = cadd(c0, c1), d1 = csub(c0, c1);
    float2 d2 = cadd(c2, c3), d3 = csub(c2, c3);
    float2 d4 = cadd(c4, c5), d5 = csub(c4, c5);
    float2 d6 = cadd(c6, c7), d7 = csub(c6, c7);
    v[0]=d0; v[1]=d4; v[2]=d2; v[3]=d6; v[4]=d1; v[5]=d5; v[6]=d3; v[7]=d7;
}

// ---------------------------------------------------------------------------
// 8x8 transpose across the 8 lanes of a group (24 SHFL.32 — wavefront optimal)
// ---------------------------------------------------------------------------
__device__ __forceinline__ void transpose8(float2 v[8], unsigned mask, int lane8){
    #pragma unroll
    for (int m = 4; m >= 1; m >>= 1){
        bool up = (lane8 & m) != 0;
        #pragma unroll
        for (int i = 0; i < 8; i++){
            if ((i & m) == 0){
                int lo = i, hi = i | m;
                float2 t = up ? v[lo] : v[hi];
                t.x = __shfl_xor_sync(mask, t.x, m);
                t.y = __shfl_xor_sync(mask, t.y, m);
                if (up) v[lo] = t; else v[hi] = t;
            }
        }
    }
}

// ---------------------------------------------------------------------------
// 64-pt FFT over 8 lanes (radix 8x8 four-step).
// Layout invariant (in AND out): element index = 8*reg + lane. Chains freely.
// twf[m-1] = e^{-2*pi*i * j*m / 64}, m = 1..7
// ---------------------------------------------------------------------------
template<int DIR>
__device__ __forceinline__ void fft64(float2 v[8], const float2 twf[7],
                                      unsigned mask, int j){
    fft8<DIR>(v);
    #pragma unroll
    for (int m = 1; m < 8; m++){
        float2 w = twf[m-1];
        if (DIR > 0) w.y = -w.y;
        v[m] = cmul(v[m], w);
    }
    transpose8(v, mask, j);
    fft8<DIR>(v);
}

// ---------------------------------------------------------------------------
// prep: Hermitian-symmetrized full-plane gate, 1/4096 folded, permuted layout
// ---------------------------------------------------------------------------
__global__ void prep_geff_kernel(const float* __restrict__ w){
    int idx = blockIdx.x * blockDim.x + threadIdx.x;
    if (idx >= CC * 64 * 64) return;
    int c   = idx >> 12;
    int rem = idx & 4095;
    int kw  = rem >> 6;
    int kh  = rem & 63;
    const float2* W = (const float2*)w;   // float2 index = (kh*33 + k)*CC + c
    float2 g;
    if (kw <= 32){
        g = W[(kh * 33 + kw) * CC + c];
        if (kw == 0 || kw == 32){
            float2 m = W[(((64 - kh) & 63) * 33 + kw) * CC + c];
            g.x = 0.5f * (g.x + m.x);
            g.y = 0.5f * (g.y - m.y);
        }
    } else {
        float2 m = W[(((64 - kh) & 63) * 33 + (64 - kw)) * CC + c];
        g.x =  m.x;
        g.y = -m.y;
    }
    const float S = 1.0f / 4096.0f;
    g.x *= S; g.y *= S;
    int pos = (c << 12) + (kw << 6) + ((kh & 7) << 3) + (kh >> 3);
    g_geff[pos] = g;
}

// ---------------------------------------------------------------------------
// main: one CTA per plane-PAIR (batches 2bp, 2bp+1 at channel c). z = x0 + i*x1.
// Full complex 2D FFT -> Hermitian gate -> inverse; Re -> plane0, Im -> plane1.
// 256 threads = 32 groups of 8 lanes; each group: 2 rows, 2 cols, 2 rows.
// ---------------------------------------------------------------------------
__global__ __launch_bounds__(256, 4)
void sgn5_kernel(const float* __restrict__ x, float* __restrict__ out){
    __shared__ __align__(16) float2 Sg[64 * 64];   // swizzled (kw, h)

    const int t    = threadIdx.x;
    const int j    = t & 7;
    const int g    = t >> 3;
    const int lane = t & 31;
    const unsigned mask = 0xFFu << (lane & 24);

    const int pc = blockIdx.x;            // bp*CC + c
    const int c  = pc % CC;
    const int bp = pc / CC;
    const float* xp0 = x + ((size_t)(2 * bp) * CC + c) * PLANE;
    const float* xp1 = xp0 + (size_t)CC * PLANE;
    float* op0 = out + ((size_t)(2 * bp) * CC + c) * PLANE;
    float* op1 = op0 + (size_t)CC * PLANE;

    // per-lane forward twiddles e^{-2pi i j*m/64}, m=1..7
    float2 twf[7];
    #pragma unroll
    for (int m = 1; m < 8; m++){
        float sv, cv;
        sincospif((float)(j * m) * (1.0f / 32.0f), &sv, &cv);
        twf[m-1] = make_float2(cv, -sv);
    }

    // ---------------- forward rows (W axis): rows g and g+32 ----------------
    #pragma unroll 1
    for (int it = 0; it < 2; it++){
        const int r = g + 32 * it;
        float2 v[8];
        #pragma unroll
        for (int n1 = 0; n1 < 8; n1++){
            int wdx = r * 64 + 8 * n1 + j;
            v[n1] = make_float2(xp0[wdx], xp1[wdx]);
        }
        fft64<-1>(v, twf, mask, j);               // v[k2] = Z[r][kw=j+8k2]
        #pragma unroll
        for (int k2 = 0; k2 < 8; k2++) Sg[swz(j + 8 * k2, r)] = v[k2];
    }
    __syncthreads();

    // ---- columns (H axis): fwd FFT -> gate -> inv FFT, chained in regs -----
    const float4* __restrict__ gbase = (const float4*)(g_geff + (size_t)c * 4096);
    #pragma unroll 1
    for (int it = 0; it < 2; it++){
        const int q = g + 32 * it;        // kw column
        float2 u[8];
        #pragma unroll
        for (int n1 = 0; n1 < 8; n1++) u[n1] = Sg[swz(q, 8 * n1 + j)];
        fft64<-1>(u, twf, mask, j);               // u[k2] = Xf[kh=j+8k2][q]
        // gate: 4x LDG.128 (permuted layout: (q*64 + j*8 + k2) float2s)
        const float4* gq = gbase + (q * 64 + j * 8) / 2;
        #pragma unroll
        for (int p = 0; p < 4; p++){
            float4 gg = gq[p];
            u[2*p]   = cmul(u[2*p],   make_float2(gg.x, gg.y));
            u[2*p+1] = cmul(u[2*p+1], make_float2(gg.z, gg.w));
        }
        fft64<1>(u, twf, mask, j);                // u[n2] = y[h=j+8n2][q]
        #pragma unroll
        for (int n2 = 0; n2 < 8; n2++) Sg[swz(q, j + 8 * n2)] = u[n2];
    }
    __syncthreads();

    // ---------------- inverse rows (W axis): Re->p0, Im->p1 -----------------
    #pragma unroll 1
    for (int it = 0; it < 2; it++){
        const int r = g + 32 * it;
        float2 v[8];
        #pragma unroll
        for (int n1 = 0; n1 < 8; n1++) v[n1] = Sg[swz(8 * n1 + j, r)];
        fft64<1>(v, twf, mask, j);                // v[k2] = z_out[r][w=j+8k2]
        #pragma unroll
        for (int k2 = 0; k2 < 8; k2++){
            int wdx = r * 64 + j + 8 * k2;
            op0[wdx] = v[k2].x;
            op1[wdx] = v[k2].y;
        }
    }
}

// ---------------------------------------------------------------------------
extern "C" void kernel_launch(void* const* d_in, const int* in_sizes, int n_in,
                              void* d_out, int out_size){
    const float* x;
    const float* w;
    if (in_sizes[0] == BB * CC * HH * WW){
        x = (const float*)d_in[0];
        w = (const float*)d_in[1];
    } else {
        x = (const float*)d_in[1];
        w = (const float*)d_in[0];
    }
    prep_geff_kernel<<<(CC * 64 * 64 + 255) / 256, 256>>>(w);
    sgn5_kernel<<<(BB / 2) * CC, 256>>>(x, (float*)d_out);
}

// round 13
// speedup vs baseline: 1.0863x; 1.0389x over previous
#include <cuda_runtime.h>
#include <math.h>

#define BB 64
#define CC 768
#define HH 64
#define WW 64
#define PLANE (HH*WW)           // 4096

// Hermitian-symmetrized full-plane gate, ortho^2 scale folded.
// Layout permuted for LDG.128 in the column pass:
//   plane element (kh, kw) stored at  [c][ kw*64 + (kh&7)*8 + (kh>>3) ]
__device__ float2 g_geff[CC * 64 * 64];

// ---------------------------------------------------------------------------
// complex helpers (scalar float2 engine)
// ---------------------------------------------------------------------------
__device__ __forceinline__ float2 cadd(float2 a, float2 b){ return make_float2(a.x+b.x, a.y+b.y); }
__device__ __forceinline__ float2 csub(float2 a, float2 b){ return make_float2(a.x-b.x, a.y-b.y); }
__device__ __forceinline__ float2 cmul(float2 a, float2 b){
    return make_float2(fmaf(a.x,b.x,-a.y*b.y), fmaf(a.x,b.y, a.y*b.x));
}
template<int DIR>
__device__ __forceinline__ float2 muli(float2 a){
    return (DIR < 0) ? make_float2(a.y, -a.x) : make_float2(-a.y, a.x);
}

// ---------------------------------------------------------------------------
// 8-point complex FFT on registers, natural order in/out. Unnormalized.
// ---------------------------------------------------------------------------
template<int DIR>
__device__ __forceinline__ void fft8(float2 v[8]){
    const float s = 0.70710678118654752440f;
    float2 b0 = cadd(v[0], v[4]);
    float2 b1 = cadd(v[1], v[5]);
    float2 b2 = cadd(v[2], v[6]);
    float2 b3 = cadd(v[3], v[7]);
    float2 b4 = csub(v[0], v[4]);
    float2 b5 = csub(v[1], v[5]);
    float2 b6 = csub(v[2], v[6]);
    float2 b7 = csub(v[3], v[7]);
    b5 = cmul(b5, make_float2( s, DIR * s));
    b6 = muli<DIR>(b6);
    b7 = cmul(b7, make_float2(-s, DIR * s));
    float2 c0 = cadd(b0, b2), c2 = csub(b0, b2);
    float2 c1 = cadd(b1, b3), c3 = csub(b1, b3);
    c3 = muli<DIR>(c3);
    float2 c4 = cadd(b4, b6), c6 = csub(b4, b6);
    float2 c5 = cadd(b5, b7), c7 = csub(b5, b7);
    c7 = muli<DIR>(c7);
    float2 d0 = cadd(c0, c1), d1 = csub(c0, c1);
    float2 d2 = cadd(c2, c3), d3 = csub(c2, c3);
    float2 d4 = cadd(c4, c5), d5 = csub(c4, c5);
    float2 d6 = cadd(c6, c7), d7 = csub(c6, c7);
    v[0]=d0; v[1]=d4; v[2]=d2; v[3]=d6; v[4]=d1; v[5]=d5; v[6]=d3; v[7]=d7;
}

// ---------------------------------------------------------------------------
// 8x8 transpose across the 8 lanes of a group (24 SHFL.32 — wavefront optimal)
// ---------------------------------------------------------------------------
__device__ __forceinline__ void transpose8(float2 v[8], int lane8){
    #pragma unroll
    for (int m = 4; m >= 1; m >>= 1){
        bool up = (lane8 & m) != 0;
        #pragma unroll
        for (int i = 0; i < 8; i++){
            if ((i & m) == 0){
                int lo = i, hi = i | m;
                float2 t = up ? v[lo] : v[hi];
                t.x = __shfl_xor_sync(0xFFFFFFFFu, t.x, m);
                t.y = __shfl_xor_sync(0xFFFFFFFFu, t.y, m);
                if (up) v[lo] = t; else v[hi] = t;
            }
        }
    }
}

// ---------------------------------------------------------------------------
// 64-pt FFT over 8 lanes (radix 8x8 four-step).
// Layout invariant (in AND out): element index = 8*reg + lane. Chains freely.
// twf[m-1] = e^{-2*pi*i * j*m / 64}, m = 1..7
// ---------------------------------------------------------------------------
template<int DIR>
__device__ __forceinline__ void fft64(float2 v[8], const float2 twf[7], int j){
    fft8<DIR>(v);
    #pragma unroll
    for (int m = 1; m < 8; m++){
        float2 w = twf[m-1];
        if (DIR > 0) w.y = -w.y;
        v[m] = cmul(v[m], w);
    }
    transpose8(v, j);
    fft8<DIR>(v);
}

// ---------------------------------------------------------------------------
// prep: Hermitian-symmetrized full-plane gate, 1/4096 folded, permuted layout
// ---------------------------------------------------------------------------
__global__ void prep_geff_kernel(const float* __restrict__ w){
    int idx = blockIdx.x * blockDim.x + threadIdx.x;
    if (idx >= CC * 64 * 64) return;
    int c   = idx >> 12;
    int rem = idx & 4095;
    int kw  = rem >> 6;
    int kh  = rem & 63;
    const float2* W = (const float2*)w;   // float2 index = (kh*33 + k)*CC + c
    float2 g;
    if (kw <= 32){
        g = W[(kh * 33 + kw) * CC + c];
        if (kw == 0 || kw == 32){
            float2 m = W[(((64 - kh) & 63) * 33 + kw) * CC + c];
            g.x = 0.5f * (g.x + m.x);
            g.y = 0.5f * (g.y - m.y);
        }
    } else {
        float2 m = W[(((64 - kh) & 63) * 33 + (64 - kw)) * CC + c];
        g.x =  m.x;
        g.y = -m.y;
    }
    const float S = 1.0f / 4096.0f;
    g.x *= S; g.y *= S;
    int pos = (c << 12) + (kw << 6) + ((kh & 7) << 3) + (kh >> 3);
    g_geff[pos] = g;
}

// ---------------------------------------------------------------------------
// main: one CTA per plane-PAIR (batches 2bp, 2bp+1 at channel c). z = x0 + i*x1.
// Full complex 2D FFT -> Hermitian gate -> inverse; Re -> plane0, Im -> plane1.
// 256 threads = 32 groups of 8 lanes; each group: 2 rows, 2 cols, 2 rows.
//
// Corner-turn buffer uses the conflict-free swizzle:
//   phys(kw, h) = (kw<<6) + (h ^ s(kw)),  s(kw) = ((kw&1)<<3) | (kw&6)
// Addresses are algebraically hoisted per pass (s is per-thread constant in
// the row passes; in the col pass the n1-dependence reduces to +-8b bases).
// ---------------------------------------------------------------------------
__global__ __launch_bounds__(256, 4)
void sgn6_kernel(const float* __restrict__ x, float* __restrict__ out){
    __shared__ __align__(16) float2 Sg[64 * 64];   // swizzled (kw, h)

    const int t  = threadIdx.x;
    const int j  = t & 7;
    const int g  = t >> 3;

    const int pc = blockIdx.x;            // bp*CC + c
    const int c  = pc % CC;
    const int bp = pc / CC;
    const float* xp0 = x + ((size_t)(2 * bp) * CC + c) * PLANE;
    const float* xp1 = xp0 + (size_t)CC * PLANE;
    float* op0 = out + ((size_t)(2 * bp) * CC + c) * PLANE;
    float* op1 = op0 + (size_t)CC * PLANE;

    // per-lane forward twiddles e^{-2pi i j*m/64}, m=1..7
    float2 twf[7];
    #pragma unroll
    for (int m = 1; m < 8; m++){
        float sv, cv;
        sincospif((float)(j * m) * (1.0f / 32.0f), &sv, &cv);
        twf[m-1] = make_float2(cv, -sv);
    }

    // row-pass swizzle constant: s(kw=j+8k2) depends only on j
    const int sj = ((j & 1) << 3) | (j & 6);
    // row-pass base (h part added per it): (j<<6) + (r ^ sj) + 512*k2
    const int jb = j << 6;

    // ---------------- forward rows (W axis): rows g and g+32 ----------------
    #pragma unroll 1
    for (int it = 0; it < 2; it++){
        const int r = g + 32 * it;
        const float* x0r = xp0 + r * 64 + j;
        const float* x1r = xp1 + r * 64 + j;
        float2 v[8];
        #pragma unroll
        for (int n1 = 0; n1 < 8; n1++)
            v[n1] = make_float2(x0r[8 * n1], x1r[8 * n1]);
        fft64<-1>(v, twf, j);                     // v[k2] = Z[r][kw=j+8k2]
        float2* sw = Sg + jb + (r ^ sj);
        #pragma unroll
        for (int k2 = 0; k2 < 8; k2++) sw[k2 << 9] = v[k2];
    }
    __syncthreads();

    // ---- columns (H axis): fwd FFT -> gate -> inv FFT, chained in regs -----
    const float4* __restrict__ gbase = (const float4*)(g_geff + (size_t)c * 4096);
    #pragma unroll 1
    for (int it = 0; it < 2; it++){
        const int q = g + 32 * it;        // kw column
        // col addresses: (q<<6) + (j^(q&6)) + 8*(n1 ^ (q&1))
        const int b8    = (q & 1) << 3;
        float2* cb      = Sg + (q << 6) + (j ^ (q & 6));
        float2* cbE     = cb + b8;        // even n1: +8*(q&1)
        float2* cbO     = cb - b8 + 8;    // odd  n1: 8 - 8*(q&1) ... base so that +8*(n1-1) lands right
        float2 u[8];
        #pragma unroll
        for (int n1 = 0; n1 < 8; n1 += 2){
            u[n1]     = cbE[n1 << 3];             // 8*n1 immediate
            u[n1 + 1] = cbO[n1 << 3];             // 8*(n1+1) - 8 = 8*n1 immediate
        }
        fft64<-1>(u, twf, j);                     // u[k2] = Xf[kh=j+8k2][q]
        // gate: 4x LDG.128 (permuted layout: (q*64 + j*8 + k2) float2s)
        const float4* gq = gbase + (q << 5) + (j << 2);
        #pragma unroll
        for (int p = 0; p < 4; p++){
            float4 gg = gq[p];
            u[2*p]   = cmul(u[2*p],   make_float2(gg.x, gg.y));
            u[2*p+1] = cmul(u[2*p+1], make_float2(gg.z, gg.w));
        }
        fft64<1>(u, twf, j);                      // u[n2] = y[h=j+8n2][q]
        #pragma unroll
        for (int n2 = 0; n2 < 8; n2 += 2){
            cbE[n2 << 3] = u[n2];
            cbO[n2 << 3] = u[n2 + 1];
        }
    }
    __syncthreads();

    // ---------------- inverse rows (W axis): Re->p0, Im->p1 -----------------
    #pragma unroll 1
    for (int it = 0; it < 2; it++){
        const int r = g + 32 * it;
        const float2* sw = Sg + jb + (r ^ sj);
        float2 v[8];
        #pragma unroll
        for (int n1 = 0; n1 < 8; n1++) v[n1] = sw[n1 << 9];
        fft64<1>(v, twf, j);                      // v[k2] = z_out[r][w=j+8k2]
        float* o0r = op0 + r * 64 + j;
        float* o1r = op1 + r * 64 + j;
        #pragma unroll
        for (int k2 = 0; k2 < 8; k2++){
            o0r[8 * k2] = v[k2].x;
            o1r[8 * k2] = v[k2].y;
        }
    }
}

// ---------------------------------------------------------------------------
extern "C" void kernel_launch(void* const* d_in, const int* in_sizes, int n_in,
                              void* d_out, int out_size){
    const float* x;
    const float* w;
    if (in_sizes[0] == BB * CC * HH * WW){
        x = (const float*)d_in[0];
        w = (const float*)d_in[1];
    } else {
        x = (const float*)d_in[1];
        w = (const float*)d_in[0];
    }
    prep_geff_kernel<<<(CC * 64 * 64 + 255) / 256, 256>>>(w);
    sgn6_kernel<<<(BB / 2) * CC, 256>>>(x, (float*)d_out);
}

// round 14
// speedup vs baseline: 1.1068x; 1.0189x over previous
#include <cuda_runtime.h>
#include <math.h>

#define BB 64
#define CC 768
#define HH 64
#define WW 64
#define PLANE (HH*WW)           // 4096

// Hermitian-symmetrized full-plane gate, ortho^2 scale folded.
// Layout permuted for LDG.128 in the column pass:
//   plane element (kh, kw) stored at  [c][ kw*64 + 8*(kh&7) + (kh>>3) ]
__device__ float2 g_geff[CC * 64 * 64];

// ---------------------------------------------------------------------------
// complex helpers (scalar float2 engine)
// ---------------------------------------------------------------------------
__device__ __forceinline__ float2 cadd(float2 a, float2 b){ return make_float2(a.x+b.x, a.y+b.y); }
__device__ __forceinline__ float2 csub(float2 a, float2 b){ return make_float2(a.x-b.x, a.y-b.y); }
__device__ __forceinline__ float2 cmul(float2 a, float2 b){
    return make_float2(fmaf(a.x,b.x,-a.y*b.y), fmaf(a.x,b.y, a.y*b.x));
}
template<int DIR>
__device__ __forceinline__ float2 muli(float2 a){
    return (DIR < 0) ? make_float2(a.y, -a.x) : make_float2(-a.y, a.x);
}

// ---------------------------------------------------------------------------
// 8-point complex FFT on registers, natural order in/out. Unnormalized.
// ---------------------------------------------------------------------------
template<int DIR>
__device__ __forceinline__ void fft8(float2 v[8]){
    const float s = 0.70710678118654752440f;
    float2 b0 = cadd(v[0], v[4]);
    float2 b1 = cadd(v[1], v[5]);
    float2 b2 = cadd(v[2], v[6]);
    float2 b3 = cadd(v[3], v[7]);
    float2 b4 = csub(v[0], v[4]);
    float2 b5 = csub(v[1], v[5]);
    float2 b6 = csub(v[2], v[6]);
    float2 b7 = csub(v[3], v[7]);
    b5 = cmul(b5, make_float2( s, DIR * s));
    b6 = muli<DIR>(b6);
    b7 = cmul(b7, make_float2(-s, DIR * s));
    float2 c0 = cadd(b0, b2), c2 = csub(b0, b2);
    float2 c1 = cadd(b1, b3), c3 = csub(b1, b3);
    c3 = muli<DIR>(c3);
    float2 c4 = cadd(b4, b6), c6 = csub(b4, b6);
    float2 c5 = cadd(b5, b7), c7 = csub(b5, b7);
    c7 = muli<DIR>(c7);
    float2 d0 = cadd(c0, c1), d1 = csub(c0, c1);
    float2 d2 = cadd(c2, c3), d3 = csub(c2, c3);
    float2 d4 = cadd(c4, c5), d5 = csub(c4, c5);
    float2 d6 = cadd(c6, c7), d7 = csub(c6, c7);
    v[0]=d0; v[1]=d4; v[2]=d2; v[3]=d6; v[4]=d1; v[5]=d5; v[6]=d3; v[7]=d7;
}

// ---------------------------------------------------------------------------
// 8x8 transpose across the 8 lanes of a group (24 SHFL.32 — wavefront optimal)
// ---------------------------------------------------------------------------
__device__ __forceinline__ void transpose8(float2 v[8], int lane8){
    #pragma unroll
    for (int m = 4; m >= 1; m >>= 1){
        bool up = (lane8 & m) != 0;
        #pragma unroll
        for (int i = 0; i < 8; i++){
            if ((i & m) == 0){
                int lo = i, hi = i | m;
                float2 t = up ? v[lo] : v[hi];
                t.x = __shfl_xor_sync(0xFFFFFFFFu, t.x, m);
                t.y = __shfl_xor_sync(0xFFFFFFFFu, t.y, m);
                if (up) v[lo] = t; else v[hi] = t;
            }
        }
    }
}

// ---------------------------------------------------------------------------
// 64-pt FFT over 8 lanes (radix 8x8 four-step).
// Layout invariant (in AND out): element index = 8*reg + lane. Chains freely.
// twf[m-1] = e^{-2*pi*i * j*m / 64}, m = 1..7
// ---------------------------------------------------------------------------
template<int DIR>
__device__ __forceinline__ void fft64(float2 v[8], const float2 twf[7], int j){
    fft8<DIR>(v);
    #pragma unroll
    for (int m = 1; m < 8; m++){
        float2 w = twf[m-1];
        if (DIR > 0) w.y = -w.y;
        v[m] = cmul(v[m], w);
    }
    transpose8(v, j);
    fft8<DIR>(v);
}

// ---------------------------------------------------------------------------
// prep (tiled): Hermitian-symmetrized gate, 1/4096 folded, permuted layout.
// Old prep gathered W with ~200KB strides (every 8B read = own 32B sector).
// New: CTA = (kw, c-block of 16); stage a [64 kh][16 c] tile in smem with
// c-coalesced loads, emit with output-index-coalesced stores.
// ---------------------------------------------------------------------------
__global__ void prep_geff_tiled(const float* __restrict__ w){
    __shared__ float2 tile[64][17];          // [kh][cc], padded
    const int kw = blockIdx.x;               // 0..63
    const int c0 = blockIdx.y * 16;          // 0..767 step 16
    const int t  = threadIdx.x;              // 256
    const float2* __restrict__ W = (const float2*)w;  // index (kh*33+k)*CC + c

    const int srckw = (kw <= 32) ? kw : 64 - kw;
    // load: rows kh, columns c0..c0+15 (coalesced in c)
    #pragma unroll
    for (int it = 0; it < 4; it++){
        int kh  = 16 * it + (t >> 4);
        int khs = (kw <= 32) ? kh : ((64 - kh) & 63);
        tile[kh][t & 15] = W[(khs * 33 + srckw) * CC + c0 + (t & 15)];
    }
    __syncthreads();

    const float S = 1.0f / 4096.0f;
    // store: p = permuted kh position (output-contiguous), 4 c's per thread
    #pragma unroll
    for (int it = 0; it < 4; it++){
        int p  = t & 63;
        int cc = 4 * it + (t >> 6);
        int kh = 8 * (p & 7) + (p >> 3);     // inverse of perm(kh)=8(kh&7)+(kh>>3)
        float2 g = tile[kh][cc];
        if (kw > 32) g.y = -g.y;             // conj branch (tile holds mirrored rows)
        if (kw == 0 || kw == 32){
            float2 m = tile[(64 - kh) & 63][cc];
            g.x = 0.5f * (g.x + m.x);
            g.y = 0.5f * (g.y - m.y);
        }
        g.x *= S; g.y *= S;
        g_geff[(size_t)(c0 + cc) * 4096 + kw * 64 + p] = g;
    }
}

// ---------------------------------------------------------------------------
// main: one CTA per plane-PAIR (batches 2bp, 2bp+1 at channel c). z = x0 + i*x1.
// Full complex 2D FFT -> Hermitian gate -> inverse; Re -> plane0, Im -> plane1.
// 256 threads = 32 groups of 8 lanes; each group: 2 rows, 2 cols, 2 rows.
// Corner-turn smem swizzle: phys(kw,h) = (kw<<6) + (h ^ s(kw)),
//   s(kw) = ((kw&1)<<3) | (kw&6)   (conflict-free for all four patterns)
// x/out accessed with streaming hints (__ldcs/__stcs) to protect the
// L2-resident gate (25 MB, re-read 32x per channel) from stream eviction.
// ---------------------------------------------------------------------------
__global__ __launch_bounds__(256, 4)
void sgn7_kernel(const float* __restrict__ x, float* __restrict__ out){
    __shared__ __align__(16) float2 Sg[64 * 64];   // swizzled (kw, h)

    const int t  = threadIdx.x;
    const int j  = t & 7;
    const int g  = t >> 3;

    const int pc = blockIdx.x;            // bp*CC + c
    const int c  = pc % CC;
    const int bp = pc / CC;
    const float* xp0 = x + ((size_t)(2 * bp) * CC + c) * PLANE;
    const float* xp1 = xp0 + (size_t)CC * PLANE;
    float* op0 = out + ((size_t)(2 * bp) * CC + c) * PLANE;
    float* op1 = op0 + (size_t)CC * PLANE;

    // per-lane forward twiddles e^{-2pi i j*m/64}, m=1..7
    float2 twf[7];
    #pragma unroll
    for (int m = 1; m < 8; m++){
        float sv, cv;
        sincospif((float)(j * m) * (1.0f / 32.0f), &sv, &cv);
        twf[m-1] = make_float2(cv, -sv);
    }

    // row-pass swizzle constant: s(kw=j+8k2) depends only on j
    const int sj = ((j & 1) << 3) | (j & 6);
    const int jb = j << 6;

    // ---------------- forward rows (W axis): rows g and g+32 ----------------
    #pragma unroll 1
    for (int it = 0; it < 2; it++){
        const int r = g + 32 * it;
        const float* x0r = xp0 + r * 64 + j;
        const float* x1r = xp1 + r * 64 + j;
        float2 v[8];
        #pragma unroll
        for (int n1 = 0; n1 < 8; n1++)
            v[n1] = make_float2(__ldcs(x0r + 8 * n1), __ldcs(x1r + 8 * n1));
        fft64<-1>(v, twf, j);                     // v[k2] = Z[r][kw=j+8k2]
        float2* sw = Sg + jb + (r ^ sj);
        #pragma unroll
        for (int k2 = 0; k2 < 8; k2++) sw[k2 << 9] = v[k2];
    }
    __syncthreads();

    // ---- columns (H axis): fwd FFT -> gate -> inv FFT, chained in regs -----
    const float4* __restrict__ gbase = (const float4*)(g_geff + (size_t)c * 4096);
    #pragma unroll 1
    for (int it = 0; it < 2; it++){
        const int q = g + 32 * it;        // kw column
        // col addresses: (q<<6) + (j^(q&6)) + 8*(n1 ^ (q&1))
        const int b8    = (q & 1) << 3;
        float2* cb      = Sg + (q << 6) + (j ^ (q & 6));
        float2* cbE     = cb + b8;
        float2* cbO     = cb - b8 + 8;
        float2 u[8];
        #pragma unroll
        for (int n1 = 0; n1 < 8; n1 += 2){
            u[n1]     = cbE[n1 << 3];
            u[n1 + 1] = cbO[n1 << 3];
        }
        fft64<-1>(u, twf, j);                     // u[k2] = Xf[kh=j+8k2][q]
        // gate: 4x LDG.128 (permuted layout: (q*64 + j*8 + k2) float2s)
        const float4* gq = gbase + (q << 5) + (j << 2);
        #pragma unroll
        for (int p = 0; p < 4; p++){
            float4 gg = gq[p];
            u[2*p]   = cmul(u[2*p],   make_float2(gg.x, gg.y));
            u[2*p+1] = cmul(u[2*p+1], make_float2(gg.z, gg.w));
        }
        fft64<1>(u, twf, j);                      // u[n2] = y[h=j+8n2][q]
        #pragma unroll
        for (int n2 = 0; n2 < 8; n2 += 2){
            cbE[n2 << 3] = u[n2];
            cbO[n2 << 3] = u[n2 + 1];
        }
    }
    __syncthreads();

    // ---------------- inverse rows (W axis): Re->p0, Im->p1 -----------------
    #pragma unroll 1
    for (int it = 0; it < 2; it++){
        const int r = g + 32 * it;
        const float2* sw = Sg + jb + (r ^ sj);
        float2 v[8];
        #pragma unroll
        for (int n1 = 0; n1 < 8; n1++) v[n1] = sw[n1 << 9];
        fft64<1>(v, twf, j);                      // v[k2] = z_out[r][w=j+8k2]
        float* o0r = op0 + r * 64 + j;
        float* o1r = op1 + r * 64 + j;
        #pragma unroll
        for (int k2 = 0; k2 < 8; k2++){
            __stcs(o0r + 8 * k2, v[k2].x);
            __stcs(o1r + 8 * k2, v[k2].y);
        }
    }
}

// ---------------------------------------------------------------------------
extern "C" void kernel_launch(void* const* d_in, const int* in_sizes, int n_in,
                              void* d_out, int out_size){
    const float* x;
    const float* w;
    if (in_sizes[0] == BB * CC * HH * WW){
        x = (const float*)d_in[0];
        w = (const float*)d_in[1];
    } else {
        x = (const float*)d_in[1];
        w = (const float*)d_in[0];
    }
    dim3 pgrid(64, CC / 16);
    prep_geff_tiled<<<pgrid, 256>>>(w);
    sgn7_kernel<<<(BB / 2) * CC, 256>>>(x, (float*)d_out);
}

// round 16
// speedup vs baseline: 1.1213x; 1.0131x over previous
#include <cuda_runtime.h>
#include <math.h>

#define BB 64
#define CC 768
#define HH 64
#define WW 64
#define PLANE (HH*WW)           // 4096

// Hermitian-symmetrized full-plane gate, ortho^2 scale folded.
// Layout permuted for LDG.128 in the column pass:
//   plane element (kh, kw) stored at  [c][ kw*64 + 8*(kh&7) + (kh>>3) ]
__device__ float2 g_geff[CC * 64 * 64];

// ---------------------------------------------------------------------------
// scalar complex helpers
// ---------------------------------------------------------------------------
__device__ __forceinline__ float2 cadd(float2 a, float2 b){ return make_float2(a.x+b.x, a.y+b.y); }
__device__ __forceinline__ float2 csub(float2 a, float2 b){ return make_float2(a.x-b.x, a.y-b.y); }
__device__ __forceinline__ float2 cmul(float2 a, float2 b){
    return make_float2(fmaf(a.x,b.x,-a.y*b.y), fmaf(a.x,b.y, a.y*b.x));
}
template<int DIR>
__device__ __forceinline__ float2 muli(float2 a){
    return (DIR < 0) ? make_float2(a.y, -a.x) : make_float2(-a.y, a.x);
}

// ---------------------------------------------------------------------------
// packed (f32x2) complex add/sub: one FADD2/FFMA2 instead of two scalar FADDs.
// No component swaps ever needed for add/sub, so none of Round-4's pswap MOV
// churn. qsub = fma(b, (-1,-1), a): bit-identical to scalar a-b.
// ---------------------------------------------------------------------------
__device__ __forceinline__ float2 qadd(float2 a, float2 b){
    float2 r;
    asm("{\n\t.reg .b64 ra, rb;\n\t"
        "mov.b64 ra, {%2, %3};\n\t"
        "mov.b64 rb, {%4, %5};\n\t"
        "add.rn.f32x2 ra, ra, rb;\n\t"
        "mov.b64 {%0, %1}, ra;\n\t}"
        : "=f"(r.x), "=f"(r.y) : "f"(a.x), "f"(a.y), "f"(b.x), "f"(b.y));
    return r;
}
__device__ __forceinline__ float2 qsub(float2 a, float2 b){
    float2 r;
    asm("{\n\t.reg .b64 ra, rb, rn;\n\t"
        "mov.b64 rn, 0xBF800000BF800000;\n\t"
        "mov.b64 ra, {%2, %3};\n\t"
        "mov.b64 rb, {%4, %5};\n\t"
        "fma.rn.f32x2 ra, rb, rn, ra;\n\t"
        "mov.b64 {%0, %1}, ra;\n\t}"
        : "=f"(r.x), "=f"(r.y) : "f"(a.x), "f"(a.y), "f"(b.x), "f"(b.y));
    return r;
}

// ---------------------------------------------------------------------------
// 8-point complex FFT, natural order in/out. Unnormalized.
// Pure add/sub butterflies packed (f32x2); the six butterflies that consume
// +-i-rotated operands stay scalar so the negations fold into FADD modifiers.
// ---------------------------------------------------------------------------
template<int DIR>
__device__ __forceinline__ void fft8(float2 v[8]){
    const float s = 0.70710678118654752440f;
    // stage 1 (stride 4)
    float2 b0 = qadd(v[0], v[4]);
    float2 b1 = qadd(v[1], v[5]);
    float2 b2 = qadd(v[2], v[6]);
    float2 b3 = qadd(v[3], v[7]);
    float2 b4 = qsub(v[0], v[4]);
    float2 b5 = qsub(v[1], v[5]);
    float2 b6 = qsub(v[2], v[6]);
    float2 b7 = qsub(v[3], v[7]);
    b5 = cmul(b5, make_float2( s, DIR * s));   // W8^{+-1}
    b7 = cmul(b7, make_float2(-s, DIR * s));   // W8^{+-3}
    float2 r6 = muli<DIR>(b6);                  // virtual (folds below)
    // stage 2 (stride 2)
    float2 c0 = qadd(b0, b2), c2 = qsub(b0, b2);
    float2 c1 = qadd(b1, b3), t3 = qsub(b1, b3);
    float2 c3 = muli<DIR>(t3);                  // virtual
    float2 c4 = cadd(b4, r6), c6 = csub(b4, r6);   // scalar: negs fold
    float2 c5 = qadd(b5, b7), u7 = qsub(b5, b7);
    float2 c7 = muli<DIR>(u7);                  // virtual
    // stage 3 (stride 1)
    float2 d0 = qadd(c0, c1), d1 = qsub(c0, c1);
    float2 d2 = cadd(c2, c3), d3 = csub(c2, c3);   // scalar: negs fold
    float2 d4 = qadd(c4, c5), d5 = qsub(c4, c5);
    float2 d6 = cadd(c6, c7), d7 = csub(c6, c7);   // scalar: negs fold
    // undo DIF bit-reversal
    v[0]=d0; v[1]=d4; v[2]=d2; v[3]=d6; v[4]=d1; v[5]=d5; v[6]=d3; v[7]=d7;
}

// ---------------------------------------------------------------------------
// 8x8 transpose across the 8 lanes of a group (24 SHFL.32 — wavefront optimal)
// ---------------------------------------------------------------------------
__device__ __forceinline__ void transpose8(float2 v[8], int lane8){
    #pragma unroll
    for (int m = 4; m >= 1; m >>= 1){
        bool up = (lane8 & m) != 0;
        #pragma unroll
        for (int i = 0; i < 8; i++){
            if ((i & m) == 0){
                int lo = i, hi = i | m;
                float2 t = up ? v[lo] : v[hi];
                t.x = __shfl_xor_sync(0xFFFFFFFFu, t.x, m);
                t.y = __shfl_xor_sync(0xFFFFFFFFu, t.y, m);
                if (up) v[lo] = t; else v[hi] = t;
            }
        }
    }
}

// ---------------------------------------------------------------------------
// 64-pt FFT over 8 lanes (radix 8x8 four-step).
// Layout invariant (in AND out): element index = 8*reg + lane. Chains freely.
// twf[m-1] = e^{-2*pi*i * j*m / 64}, m = 1..7
// ---------------------------------------------------------------------------
template<int DIR>
__device__ __forceinline__ void fft64(float2 v[8], const float2 twf[7], int j){
    fft8<DIR>(v);
    #pragma unroll
    for (int m = 1; m < 8; m++){
        float2 w = twf[m-1];
        if (DIR > 0) w.y = -w.y;
        v[m] = cmul(v[m], w);
    }
    transpose8(v, j);
    fft8<DIR>(v);
}

// ---------------------------------------------------------------------------
// prep (tiled): Hermitian-symmetrized gate, 1/4096 folded, permuted layout.
// CTA = (kw, c-block of 16); [64 kh][16 c] smem tile, coalesced both ways.
// ---------------------------------------------------------------------------
__global__ void prep_geff_tiled(const float* __restrict__ w){
    __shared__ float2 tile[64][17];          // [kh][cc], padded
    const int kw = blockIdx.x;               // 0..63
    const int c0 = blockIdx.y * 16;          // 0..767 step 16
    const int t  = threadIdx.x;              // 256
    const float2* __restrict__ W = (const float2*)w;  // index (kh*33+k)*CC + c

    const int srckw = (kw <= 32) ? kw : 64 - kw;
    #pragma unroll
    for (int it = 0; it < 4; it++){
        int kh  = 16 * it + (t >> 4);
        int khs = (kw <= 32) ? kh : ((64 - kh) & 63);
        tile[kh][t & 15] = W[(khs * 33 + srckw) * CC + c0 + (t & 15)];
    }
    __syncthreads();

    const float S = 1.0f / 4096.0f;
    #pragma unroll
    for (int it = 0; it < 4; it++){
        int p  = t & 63;
        int cc = 4 * it + (t >> 6);
        int kh = 8 * (p & 7) + (p >> 3);     // inverse of perm(kh)=8(kh&7)+(kh>>3)
        float2 g = tile[kh][cc];
        if (kw > 32) g.y = -g.y;             // conj branch (tile holds mirrored rows)
        if (kw == 0 || kw == 32){
            float2 m = tile[(64 - kh) & 63][cc];
            g.x = 0.5f * (g.x + m.x);
            g.y = 0.5f * (g.y - m.y);
        }
        g.x *= S; g.y *= S;
        g_geff[(size_t)(c0 + cc) * 4096 + kw * 64 + p] = g;
    }
}

// ---------------------------------------------------------------------------
// main: one CTA per plane-PAIR (batches 2bp, 2bp+1 at channel c). z = x0 + i*x1.
// Full complex 2D FFT -> Hermitian gate -> inverse; Re -> plane0, Im -> plane1.
// 256 threads = 32 groups of 8 lanes; each group: 2 rows, 2 cols, 2 rows.
// Corner-turn smem swizzle: phys(kw,h) = (kw<<6) + (h ^ s(kw)),
//   s(kw) = ((kw&1)<<3) | (kw&6)   (conflict-free for all four patterns)
// ---------------------------------------------------------------------------
__global__ __launch_bounds__(256, 4)
void sgn8_kernel(const float* __restrict__ x, float* __restrict__ out){
    __shared__ __align__(16) float2 Sg[64 * 64];   // swizzled (kw, h)

    const int t  = threadIdx.x;
    const int j  = t & 7;
    const int g  = t >> 3;

    const int pc = blockIdx.x;            // bp*CC + c
    const int c  = pc % CC;
    const int bp = pc / CC;
    const float* xp0 = x + ((size_t)(2 * bp) * CC + c) * PLANE;
    const float* xp1 = xp0 + (size_t)CC * PLANE;
    float* op0 = out + ((size_t)(2 * bp) * CC + c) * PLANE;
    float* op1 = op0 + (size_t)CC * PLANE;

    // per-lane forward twiddles e^{-2pi i j*m/64}, m=1..7
    float2 twf[7];
    #pragma unroll
    for (int m = 1; m < 8; m++){
        float sv, cv;
        sincospif((float)(j * m) * (1.0f / 32.0f), &sv, &cv);
        twf[m-1] = make_float2(cv, -sv);
    }

    // row-pass swizzle constant: s(kw=j+8k2) depends only on j
    const int sj = ((j & 1) << 3) | (j & 6);
    const int jb = j << 6;

    // ---------------- forward rows (W axis): rows g and g+32 ----------------
    #pragma unroll 1
    for (int it = 0; it < 2; it++){
        const int r = g + 32 * it;
        const float* x0r = xp0 + r * 64 + j;
        const float* x1r = xp1 + r * 64 + j;
        float2 v[8];
        #pragma unroll
        for (int n1 = 0; n1 < 8; n1++)
            v[n1] = make_float2(__ldcs(x0r + 8 * n1), __ldcs(x1r + 8 * n1));
        fft64<-1>(v, twf, j);                     // v[k2] = Z[r][kw=j+8k2]
        float2* sw = Sg + jb + (r ^ sj);
        #pragma unroll
        for (int k2 = 0; k2 < 8; k2++) sw[k2 << 9] = v[k2];
    }
    __syncthreads();

    // ---- columns (H axis): fwd FFT -> gate -> inv FFT, chained in regs -----
    const float4* __restrict__ gbase = (const float4*)(g_geff + (size_t)c * 4096);
    #pragma unroll 1
    for (int it = 0; it < 2; it++){
        const int q = g + 32 * it;        // kw column
        // col addresses: (q<<6) + (j^(q&6)) + 8*(n1 ^ (q&1))
        const int b8    = (q & 1) << 3;
        float2* cb      = Sg + (q << 6) + (j ^ (q & 6));
        float2* cbE     = cb + b8;
        float2* cbO     = cb - b8 + 8;
        float2 u[8];
        #pragma unroll
        for (int n1 = 0; n1 < 8; n1 += 2){
            u[n1]     = cbE[n1 << 3];
            u[n1 + 1] = cbO[n1 << 3];
        }
        fft64<-1>(u, twf, j);                     // u[k2] = Xf[kh=j+8k2][q]
        // gate: 4x LDG.128 (permuted layout: (q*64 + j*8 + k2) float2s)
        const float4* gq = gbase + (q << 5) + (j << 2);
        #pragma unroll
        for (int p = 0; p < 4; p++){
            float4 gg = gq[p];
            u[2*p]   = cmul(u[2*p],   make_float2(gg.x, gg.y));
            u[2*p+1] = cmul(u[2*p+1], make_float2(gg.z, gg.w));
        }
        fft64<1>(u, twf, j);                      // u[n2] = y[h=j+8n2][q]
        #pragma unroll
        for (int n2 = 0; n2 < 8; n2 += 2){
            cbE[n2 << 3] = u[n2];
            cbO[n2 << 3] = u[n2 + 1];
        }
    }
    __syncthreads();

    // ---------------- inverse rows (W axis): Re->p0, Im->p1 -----------------
    #pragma unroll 1
    for (int it = 0; it < 2; it++){
        const int r = g + 32 * it;
        const float2* sw = Sg + jb + (r ^ sj);
        float2 v[8];
        #pragma unroll
        for (int n1 = 0; n1 < 8; n1++) v[n1] = sw[n1 << 9];
        fft64<1>(v, twf, j);                      // v[k2] = z_out[r][w=j+8k2]
        float* o0r = op0 + r * 64 + j;
        float* o1r = op1 + r * 64 + j;
        #pragma unroll
        for (int k2 = 0; k2 < 8; k2++){
            __stcs(o0r + 8 * k2, v[k2].x);
            __stcs(o1r + 8 * k2, v[k2].y);
        }
    }
}

// ---------------------------------------------------------------------------
extern "C" void kernel_launch(void* const* d_in, const int* in_sizes, int n_in,
                              void* d_out, int out_size){
    const float* x;
    const float* w;
    if (in_sizes[0] == BB * CC * HH * WW){
        x = (const float*)d_in[0];
        w = (const float*)d_in[1];
    } else {
        x = (const float*)d_in[1];
        w = (const float*)d_in[0];
    }
    dim3 pgrid(64, CC / 16);
    prep_geff_tiled<<<pgrid, 256>>>(w);
    sgn8_kernel<<<(BB / 2) * CC, 256>>>(x, (float*)d_out);
}